// round 11
// baseline (speedup 1.0000x reference)
#include <cuda_runtime.h>
#include <math.h>

#define B_    16
#define T_    64
#define N_    256
#define D_    64
#define TWOD_ 128
#define ND_   16384   // N_*D_ : element stride between consecutive t rows

// Pre-transposed weights: W12t,W13t,W14t as [128][64]; W15t,W16t as [64][64]
__device__ float g_Wt[3 * TWOD_ * D_ + 2 * D_ * D_];   // 32768 floats

__global__ void transpose_weights(const float* __restrict__ W12,
                                  const float* __restrict__ W13,
                                  const float* __restrict__ W14,
                                  const float* __restrict__ W15,
                                  const float* __restrict__ W16)
{
    int idx = blockIdx.x * blockDim.x + threadIdx.x;
    if (idx < 8192) {
        int j = idx >> 7, c = idx & 127;
        g_Wt[c * 64 + j] = W12[idx];
    } else if (idx < 16384) {
        int k = idx - 8192; int j = k >> 7, c = k & 127;
        g_Wt[8192 + c * 64 + j] = W13[k];
    } else if (idx < 24576) {
        int k = idx - 16384; int j = k >> 7, c = k & 127;
        g_Wt[16384 + c * 64 + j] = W14[k];
    } else if (idx < 28672) {
        int k = idx - 24576; int j = k >> 6, c = k & 63;
        g_Wt[24576 + c * 64 + j] = W15[k];
    } else if (idx < 32768) {
        int k = idx - 28672; int j = k >> 6, c = k & 63;
        g_Wt[28672 + c * 64 + j] = W16[k];
    }
}

__device__ __forceinline__ float gelu_f(float x) {
    // exact erf GELU (matches jax.nn.gelu(approximate=False) / torch F.gelu default)
    return 0.5f * x * (1.0f + erff(x * 0.7071067811865475f));
}

// SMEM layout (floats):
//   sH  @ 0      : 8704  (H tile 64 x 128 with row stride 132; later reused:
//                         sOut 64x64 stride 68 @0, o1 64x64 stride 68 @4352)
//   sWc @ 8704   : 2048  (32 x 64 weight chunk, [c][j])
//   sQ  @ 10752  : 4096  (64 x 64, stride 64)
//   sK  @ 14848  : 4096
//   sV  @ 18944  : 4096
// total 23040 floats = 92160 bytes -> 2 CTAs/SM
#define SMEM_FLOATS 23040

__global__ __launch_bounds__(256, 2)
void tam_kernel(const float* __restrict__ X,  const float* __restrict__ STE,
                const float* __restrict__ b12, const float* __restrict__ b13,
                const float* __restrict__ b14, const float* __restrict__ b15,
                const float* __restrict__ b16, float* __restrict__ out)
{
    extern __shared__ float sm[];
    float* sH  = sm;
    float* sWc = sm + 8704;
    float* sQ  = sm + 10752;
    float* sK  = sm + 14848;
    float* sV  = sm + 18944;

    const int n = blockIdx.x, b = blockIdx.y;
    const int tid = threadIdx.x;
    const int baseX = (b * T_ * N_ + n) * D_;   // element offset of (b, t=0, n, 0)

    // ---------------- load H = [X | STE] : 64 rows x 128, stride 132 ----------------
    for (int i = tid; i < T_ * TWOD_; i += 256) {
        int t = i >> 7, c = i & 127;
        int g = baseX + t * ND_ + (c & 63);
        sH[t * 132 + c] = (c < 64) ? X[g] : STE[g];
    }
    __syncthreads();

    const int jb = tid & 7;        // 8 j-blocks of 8 outputs
    const int tb = tid >> 3;       // 32 t-blocks of 2 rows
    const int j0 = jb * 8;
    const int t0 = tb * 2;

    // ---------------- QKV projections: q/k/v = gelu(H @ W^T + b) ----------------
    #pragma unroll
    for (int m = 0; m < 3; m++) {
        const float* Wt   = g_Wt + m * 8192;                       // [128][64]
        const float* bias = (m == 0) ? b12 : (m == 1) ? b13 : b14;
        float* dst        = (m == 0) ? sQ  : (m == 1) ? sK  : sV;

        float a0[8], a1[8];
        #pragma unroll
        for (int jj = 0; jj < 8; jj++) { a0[jj] = 0.f; a1[jj] = 0.f; }

        for (int ch = 0; ch < 4; ch++) {               // 4 chunks of 32 c-rows
            #pragma unroll
            for (int i = 0; i < 8; i++)
                sWc[tid + i * 256] = Wt[ch * 2048 + tid + i * 256];
            __syncthreads();

            #pragma unroll 8
            for (int c = 0; c < 32; c++) {
                int cc = (ch << 5) + c;
                float h0 = sH[t0 * 132 + cc];
                float h1 = sH[t0 * 132 + 132 + cc];
                float4 wA = *(const float4*)&sWc[c * 64 + j0];
                float4 wB = *(const float4*)&sWc[c * 64 + j0 + 4];
                a0[0] += h0 * wA.x; a0[1] += h0 * wA.y; a0[2] += h0 * wA.z; a0[3] += h0 * wA.w;
                a0[4] += h0 * wB.x; a0[5] += h0 * wB.y; a0[6] += h0 * wB.z; a0[7] += h0 * wB.w;
                a1[0] += h1 * wA.x; a1[1] += h1 * wA.y; a1[2] += h1 * wA.z; a1[3] += h1 * wA.w;
                a1[4] += h1 * wB.x; a1[5] += h1 * wB.y; a1[6] += h1 * wB.z; a1[7] += h1 * wB.w;
            }
            __syncthreads();
        }

        #pragma unroll
        for (int jj = 0; jj < 8; jj++) {
            float bj = bias[j0 + jj];
            dst[t0 * 64 + j0 + jj]       = gelu_f(a0[jj] + bj);
            dst[(t0 + 1) * 64 + j0 + jj] = gelu_f(a1[jj] + bj);
        }
    }
    __syncthreads();

    // ---------------- causal attention per (head, query t), softmax over s<=t ----------------
    {
        const int h   = tid & 7;
        const int tq0 = tid >> 3;
        const float scale = 0.35355339059327376f;  // 1/sqrt(8)
        float* sO = sH;                            // output tile, stride 68

        #pragma unroll
        for (int p = 0; p < 2; p++) {
            const int tq = tq0 + p * 32;
            const float4 qa = *(const float4*)&sQ[tq * 64 + h * 8];
            const float4 qb = *(const float4*)&sQ[tq * 64 + h * 8 + 4];

            // pass 1: row max
            float mx = -1e30f;
            #pragma unroll 4
            for (int s = 0; s <= tq; s++) {
                const float4 ka = *(const float4*)&sK[s * 64 + h * 8];
                const float4 kb = *(const float4*)&sK[s * 64 + h * 8 + 4];
                float l = qa.x*ka.x + qa.y*ka.y + qa.z*ka.z + qa.w*ka.w
                        + qb.x*kb.x + qb.y*kb.y + qb.z*kb.z + qb.w*kb.w;
                mx = fmaxf(mx, l * scale);
            }

            // pass 2: recompute logits, accumulate exp-weighted V
            float sum = 0.f;
            float acc[8];
            #pragma unroll
            for (int jj = 0; jj < 8; jj++) acc[jj] = 0.f;

            #pragma unroll 4
            for (int s = 0; s <= tq; s++) {
                const float4 ka = *(const float4*)&sK[s * 64 + h * 8];
                const float4 kb = *(const float4*)&sK[s * 64 + h * 8 + 4];
                float l = qa.x*ka.x + qa.y*ka.y + qa.z*ka.z + qa.w*ka.w
                        + qb.x*kb.x + qb.y*kb.y + qb.z*kb.z + qb.w*kb.w;
                float e = __expf(l * scale - mx);
                sum += e;
                const float4 va = *(const float4*)&sV[s * 64 + h * 8];
                const float4 vb = *(const float4*)&sV[s * 64 + h * 8 + 4];
                acc[0] += e * va.x; acc[1] += e * va.y; acc[2] += e * va.z; acc[3] += e * va.w;
                acc[4] += e * vb.x; acc[5] += e * vb.y; acc[6] += e * vb.z; acc[7] += e * vb.w;
            }

            float inv = 1.0f / sum;
            #pragma unroll
            for (int jj = 0; jj < 8; jj++)
                sO[tq * 68 + h * 8 + jj] = acc[jj] * inv;
        }
    }
    __syncthreads();

    // ---------------- output MLP stage 1: o1 = gelu(attn_out @ W15^T + b15) ----------------
    float* sO = sH;            // input, stride 68
    float* sM = sH + 4352;     // hidden, stride 68
    {
        const float* Wt = g_Wt + 24576;    // W15t [64][64]
        float a0[8], a1[8];
        #pragma unroll
        for (int jj = 0; jj < 8; jj++) { a0[jj] = 0.f; a1[jj] = 0.f; }

        for (int ch = 0; ch < 2; ch++) {
            #pragma unroll
            for (int i = 0; i < 8; i++)
                sWc[tid + i * 256] = Wt[ch * 2048 + tid + i * 256];
            __syncthreads();

            #pragma unroll 8
            for (int c = 0; c < 32; c++) {
                int cc = (ch << 5) + c;
                float h0 = sO[t0 * 68 + cc];
                float h1 = sO[t0 * 68 + 68 + cc];
                float4 wA = *(const float4*)&sWc[c * 64 + j0];
                float4 wB = *(const float4*)&sWc[c * 64 + j0 + 4];
                a0[0] += h0 * wA.x; a0[1] += h0 * wA.y; a0[2] += h0 * wA.z; a0[3] += h0 * wA.w;
                a0[4] += h0 * wB.x; a0[5] += h0 * wB.y; a0[6] += h0 * wB.z; a0[7] += h0 * wB.w;
                a1[0] += h1 * wA.x; a1[1] += h1 * wA.y; a1[2] += h1 * wA.z; a1[3] += h1 * wA.w;
                a1[4] += h1 * wB.x; a1[5] += h1 * wB.y; a1[6] += h1 * wB.z; a1[7] += h1 * wB.w;
            }
            __syncthreads();
        }

        #pragma unroll
        for (int jj = 0; jj < 8; jj++) {
            float bj = b15[j0 + jj];
            sM[t0 * 68 + j0 + jj]       = gelu_f(a0[jj] + bj);
            sM[(t0 + 1) * 68 + j0 + jj] = gelu_f(a1[jj] + bj);
        }
        __syncthreads();
    }

    // ---------------- output MLP stage 2: result = o1 @ W16^T + b16 -> GMEM ----------------
    {
        const float* Wt = g_Wt + 28672;    // W16t [64][64]
        float a0[8], a1[8];
        #pragma unroll
        for (int jj = 0; jj < 8; jj++) { a0[jj] = 0.f; a1[jj] = 0.f; }

        for (int ch = 0; ch < 2; ch++) {
            #pragma unroll
            for (int i = 0; i < 8; i++)
                sWc[tid + i * 256] = Wt[ch * 2048 + tid + i * 256];
            __syncthreads();

            #pragma unroll 8
            for (int c = 0; c < 32; c++) {
                int cc = (ch << 5) + c;
                float h0 = sM[t0 * 68 + cc];
                float h1 = sM[t0 * 68 + 68 + cc];
                float4 wA = *(const float4*)&sWc[c * 64 + j0];
                float4 wB = *(const float4*)&sWc[c * 64 + j0 + 4];
                a0[0] += h0 * wA.x; a0[1] += h0 * wA.y; a0[2] += h0 * wA.z; a0[3] += h0 * wA.w;
                a0[4] += h0 * wB.x; a0[5] += h0 * wB.y; a0[6] += h0 * wB.z; a0[7] += h0 * wB.w;
                a1[0] += h1 * wA.x; a1[1] += h1 * wA.y; a1[2] += h1 * wA.z; a1[3] += h1 * wA.w;
                a1[4] += h1 * wB.x; a1[5] += h1 * wB.y; a1[6] += h1 * wB.z; a1[7] += h1 * wB.w;
            }
            __syncthreads();
        }

        float4 r0a, r0b, r1a, r1b;
        r0a.x = a0[0] + b16[j0+0]; r0a.y = a0[1] + b16[j0+1];
        r0a.z = a0[2] + b16[j0+2]; r0a.w = a0[3] + b16[j0+3];
        r0b.x = a0[4] + b16[j0+4]; r0b.y = a0[5] + b16[j0+5];
        r0b.z = a0[6] + b16[j0+6]; r0b.w = a0[7] + b16[j0+7];
        r1a.x = a1[0] + b16[j0+0]; r1a.y = a1[1] + b16[j0+1];
        r1a.z = a1[2] + b16[j0+2]; r1a.w = a1[3] + b16[j0+3];
        r1b.x = a1[4] + b16[j0+4]; r1b.y = a1[5] + b16[j0+5];
        r1b.z = a1[6] + b16[j0+6]; r1b.w = a1[7] + b16[j0+7];

        int g0 = baseX + t0 * ND_ + j0;
        int g1 = g0 + ND_;
        *(float4*)&out[g0]     = r0a;
        *(float4*)&out[g0 + 4] = r0b;
        *(float4*)&out[g1]     = r1a;
        *(float4*)&out[g1 + 4] = r1b;
    }
}

extern "C" void kernel_launch(void* const* d_in, const int* in_sizes, int n_in,
                              void* d_out, int out_size)
{
    const float* X   = (const float*)d_in[0];
    const float* STE = (const float*)d_in[1];
    const float* W12 = (const float*)d_in[2];
    const float* b12 = (const float*)d_in[3];
    const float* W13 = (const float*)d_in[4];
    const float* b13 = (const float*)d_in[5];
    const float* W14 = (const float*)d_in[6];
    const float* b14 = (const float*)d_in[7];
    const float* W15 = (const float*)d_in[8];
    const float* b15 = (const float*)d_in[9];
    const float* W16 = (const float*)d_in[10];
    const float* b16 = (const float*)d_in[11];
    float* out = (float*)d_out;

    cudaFuncSetAttribute(tam_kernel,
                         cudaFuncAttributeMaxDynamicSharedMemorySize,
                         SMEM_FLOATS * (int)sizeof(float));

    transpose_weights<<<128, 256>>>(W12, W13, W14, W15, W16);

    dim3 grid(N_, B_);
    tam_kernel<<<grid, 256, SMEM_FLOATS * sizeof(float)>>>(
        X, STE, b12, b13, b14, b15, b16, out);
}

// round 12
// speedup vs baseline: 1.7150x; 1.7150x over previous
#include <cuda_runtime.h>
#include <math.h>

#define B_    16
#define T_    64
#define N_    256
#define D_    64
#define TWOD_ 128
#define ND_   16384   // N_*D_ : element stride between consecutive t rows

// Pre-transposed weights: W12t,W13t,W14t as [128][64]; W15t,W16t as [64][64]
__device__ __align__(16) float g_Wt[3 * TWOD_ * D_ + 2 * D_ * D_];   // 32768 floats

__global__ void transpose_weights(const float* __restrict__ W12,
                                  const float* __restrict__ W13,
                                  const float* __restrict__ W14,
                                  const float* __restrict__ W15,
                                  const float* __restrict__ W16)
{
    int idx = blockIdx.x * blockDim.x + threadIdx.x;
    if (idx < 8192) {
        int j = idx >> 7, c = idx & 127;
        g_Wt[c * 64 + j] = W12[idx];
    } else if (idx < 16384) {
        int k = idx - 8192; int j = k >> 7, c = k & 127;
        g_Wt[8192 + c * 64 + j] = W13[k];
    } else if (idx < 24576) {
        int k = idx - 16384; int j = k >> 7, c = k & 127;
        g_Wt[16384 + c * 64 + j] = W14[k];
    } else if (idx < 28672) {
        int k = idx - 24576; int j = k >> 6, c = k & 63;
        g_Wt[24576 + c * 64 + j] = W15[k];
    } else if (idx < 32768) {
        int k = idx - 28672; int j = k >> 6, c = k & 63;
        g_Wt[28672 + c * 64 + j] = W16[k];
    }
}

// ---------------- packed fp32x2 helpers (sm_103a FFMA2 path, PTX-only) ----------------
__device__ __forceinline__ unsigned long long pk2(float v) {
    unsigned long long r;
    asm("mov.b64 %0, {%1, %2};" : "=l"(r) : "f"(v), "f"(v));
    return r;
}
__device__ __forceinline__ void upk2(unsigned long long v, float& lo, float& hi) {
    asm("mov.b64 {%0, %1}, %2;" : "=f"(lo), "=f"(hi) : "l"(v));
}
__device__ __forceinline__ unsigned long long fma2(unsigned long long a,
                                                   unsigned long long b,
                                                   unsigned long long c) {
    unsigned long long d;
    asm("fma.rn.f32x2 %0, %1, %2, %3;" : "=l"(d) : "l"(a), "l"(b), "l"(c));
    return d;
}
__device__ __forceinline__ unsigned long long mul2(unsigned long long a,
                                                   unsigned long long b) {
    unsigned long long d;
    asm("mul.rn.f32x2 %0, %1, %2;" : "=l"(d) : "l"(a), "l"(b));
    return d;
}

__device__ __forceinline__ float gelu_f(float x) {
    // exact erf GELU (matches jax.nn.gelu(approximate=False))
    return 0.5f * x * (1.0f + erff(x * 0.7071067811865475f));
}

// epilogue: unpack 4 packed accumulators -> 8 outputs at j0..j0+3 and j0+32..j0+35
__device__ __forceinline__ void epi_store(float* dst_row,
                                          const unsigned long long acc[4],
                                          const float* __restrict__ bias,
                                          int j0, bool do_gelu)
{
    #pragma unroll
    for (int p = 0; p < 4; p++) {
        int j = (p < 2) ? (j0 + p * 2) : (j0 + 32 + (p - 2) * 2);
        float f0, f1;
        upk2(acc[p], f0, f1);
        f0 += bias[j];
        f1 += bias[j + 1];
        if (do_gelu) { f0 = gelu_f(f0); f1 = gelu_f(f1); }
        dst_row[j]     = f0;
        dst_row[j + 1] = f1;
    }
}

// SMEM layout (floats):
//   sH  @ 0     : 8704  (H 64x132=8448; reused: sO 64x68 @[0..4352), W16 buf @[4352..8448))
//   sWc @ 8704  : 6144  (QKV chunk: wQ/wK/wV 32x64 each; later W15t full in [0..4096))
//   sQ  @ 14848 : 4096  (later sM 64x68=4352, spilling into sK start -- sK dead by then)
//   sK  @ 18944 : 4096
//   sV  @ 23040 : 4096
// total 27136 floats = 108544 B -> 2 CTAs/SM (217 KB of 228 KB)
#define SMEM_FLOATS 27136

__global__ __launch_bounds__(256, 2)
void tam_kernel(const float* __restrict__ X,  const float* __restrict__ STE,
                const float* __restrict__ b12, const float* __restrict__ b13,
                const float* __restrict__ b14, const float* __restrict__ b15,
                const float* __restrict__ b16, float* __restrict__ out)
{
    extern __shared__ float sm[];
    float* sH  = sm;
    float* sWc = sm + 8704;
    float* sQ  = sm + 14848;
    float* sK  = sm + 18944;
    float* sV  = sm + 23040;

    const int n = blockIdx.x, b = blockIdx.y;
    const int tid = threadIdx.x;
    const int baseX = (b * T_ * N_ + n) * D_;

    // ---------------- load H = [X | STE] : 64 rows x 128, stride 132 ----------------
    for (int i = tid; i < T_ * TWOD_; i += 256) {
        int t = i >> 7, c = i & 127;
        int g = baseX + t * ND_ + (c & 63);
        sH[t * 132 + c] = (c < 64) ? X[g] : STE[g];
    }
    __syncthreads();

    const int jb = tid & 7;        // 8 j-blocks
    const int tb = tid >> 3;       // 32 t-blocks of 2 rows
    const int j0 = jb * 4;         // thread owns j0..j0+3 and j0+32..j0+35
    const int t0 = tb * 2;

    const float* hR0 = sH + t0 * 132;
    const float* hR1 = hR0 + 132;

    // ---------------- fused QKV: q/k/v = gelu(H @ W^T + b), single pass over H ----------------
    unsigned long long aQ[2][4], aK[2][4], aV[2][4];
    #pragma unroll
    for (int r = 0; r < 2; r++)
        #pragma unroll
        for (int p = 0; p < 4; p++) { aQ[r][p] = 0ull; aK[r][p] = 0ull; aV[r][p] = 0ull; }

    for (int ch = 0; ch < 4; ch++) {               // 4 chunks of 32 c-rows
        // cooperative load of 32x64 chunk of each of W12t/W13t/W14t (6144 floats)
        #pragma unroll
        for (int i = 0; i < 6; i++) {
            int k = i * 256 + tid;                 // float4 index 0..1535
            int m = k >> 9, off = (k & 511) << 2;
            *(float4*)&sWc[m * 2048 + off] =
                *(const float4*)&g_Wt[m * 8192 + ch * 2048 + off];
        }
        __syncthreads();

        const float* wq = sWc;
        const float* wk = sWc + 2048;
        const float* wv = sWc + 4096;

        #pragma unroll 2
        for (int c4 = 0; c4 < 8; c4++) {
            int cc = (ch << 5) + (c4 << 2);
            float4 h0v = *(const float4*)(hR0 + cc);
            float4 h1v = *(const float4*)(hR1 + cc);
            float h0a[4] = {h0v.x, h0v.y, h0v.z, h0v.w};
            float h1a[4] = {h1v.x, h1v.y, h1v.z, h1v.w};
            #pragma unroll
            for (int i = 0; i < 4; i++) {
                int c = (c4 << 2) + i;
                ulonglong2 q0 = *(const ulonglong2*)(wq + c * 64 + j0);
                ulonglong2 q1 = *(const ulonglong2*)(wq + c * 64 + j0 + 32);
                ulonglong2 k0 = *(const ulonglong2*)(wk + c * 64 + j0);
                ulonglong2 k1 = *(const ulonglong2*)(wk + c * 64 + j0 + 32);
                ulonglong2 v0 = *(const ulonglong2*)(wv + c * 64 + j0);
                ulonglong2 v1 = *(const ulonglong2*)(wv + c * 64 + j0 + 32);
                unsigned long long H0 = pk2(h0a[i]);
                unsigned long long H1 = pk2(h1a[i]);
                aQ[0][0] = fma2(H0, q0.x, aQ[0][0]); aQ[0][1] = fma2(H0, q0.y, aQ[0][1]);
                aQ[0][2] = fma2(H0, q1.x, aQ[0][2]); aQ[0][3] = fma2(H0, q1.y, aQ[0][3]);
                aQ[1][0] = fma2(H1, q0.x, aQ[1][0]); aQ[1][1] = fma2(H1, q0.y, aQ[1][1]);
                aQ[1][2] = fma2(H1, q1.x, aQ[1][2]); aQ[1][3] = fma2(H1, q1.y, aQ[1][3]);
                aK[0][0] = fma2(H0, k0.x, aK[0][0]); aK[0][1] = fma2(H0, k0.y, aK[0][1]);
                aK[0][2] = fma2(H0, k1.x, aK[0][2]); aK[0][3] = fma2(H0, k1.y, aK[0][3]);
                aK[1][0] = fma2(H1, k0.x, aK[1][0]); aK[1][1] = fma2(H1, k0.y, aK[1][1]);
                aK[1][2] = fma2(H1, k1.x, aK[1][2]); aK[1][3] = fma2(H1, k1.y, aK[1][3]);
                aV[0][0] = fma2(H0, v0.x, aV[0][0]); aV[0][1] = fma2(H0, v0.y, aV[0][1]);
                aV[0][2] = fma2(H0, v1.x, aV[0][2]); aV[0][3] = fma2(H0, v1.y, aV[0][3]);
                aV[1][0] = fma2(H1, v0.x, aV[1][0]); aV[1][1] = fma2(H1, v0.y, aV[1][1]);
                aV[1][2] = fma2(H1, v1.x, aV[1][2]); aV[1][3] = fma2(H1, v1.y, aV[1][3]);
            }
        }
        __syncthreads();
    }

    #pragma unroll
    for (int r = 0; r < 2; r++) {
        epi_store(sQ + (t0 + r) * 64, aQ[r], b12, j0, true);
        epi_store(sK + (t0 + r) * 64, aK[r], b13, j0, true);
        epi_store(sV + (t0 + r) * 64, aV[r], b14, j0, true);
    }
    __syncthreads();

    // ---------------- overlap: load W15 -> sWc[0..4096), W16 -> sH[4352..8448) ----------------
    #pragma unroll
    for (int i = 0; i < 4; i++) {
        int k = (i * 256 + tid) << 2;              // float offset 0..4092
        *(float4*)&sWc[k]        = *(const float4*)&g_Wt[24576 + k];
        *(float4*)&sH[4352 + k]  = *(const float4*)&g_Wt[28672 + k];
    }

    // ---------------- causal attention, single pass, no max subtraction ----------------
    // Logits are O(10) at most (GELU-bounded q,k, d=8) -> exp() cannot overflow fp32;
    // softmax is shift-invariant so skipping the max pass is exact up to fp rounding.
    {
        const int h8  = (tid & 7) * 8;
        const int tq0 = tid >> 3;
        const float scale = 0.35355339059327376f;  // 1/sqrt(8)
        float* sO = sH;                            // output tile, stride 68 (in [0..4352))

        #pragma unroll
        for (int p = 0; p < 2; p++) {
            const int tq = tq0 + p * 32;
            ulonglong2 qa = *(const ulonglong2*)&sQ[tq * 64 + h8];
            ulonglong2 qb = *(const ulonglong2*)&sQ[tq * 64 + h8 + 4];
            unsigned long long acc0 = 0, acc1 = 0, acc2 = 0, acc3 = 0;
            float sum = 0.f;
            #pragma unroll 2
            for (int s = 0; s <= tq; s++) {
                ulonglong2 ka = *(const ulonglong2*)&sK[s * 64 + h8];
                ulonglong2 kb = *(const ulonglong2*)&sK[s * 64 + h8 + 4];
                unsigned long long d = mul2(qa.x, ka.x);
                d = fma2(qa.y, ka.y, d);
                d = fma2(qb.x, kb.x, d);
                d = fma2(qb.y, kb.y, d);
                float dl, dh; upk2(d, dl, dh);
                float e = __expf((dl + dh) * scale);
                sum += e;
                unsigned long long E = pk2(e);
                ulonglong2 va = *(const ulonglong2*)&sV[s * 64 + h8];
                ulonglong2 vb = *(const ulonglong2*)&sV[s * 64 + h8 + 4];
                acc0 = fma2(E, va.x, acc0); acc1 = fma2(E, va.y, acc1);
                acc2 = fma2(E, vb.x, acc2); acc3 = fma2(E, vb.y, acc3);
            }
            float inv = 1.0f / sum;
            float f0, f1;
            float4 o;
            upk2(acc0, f0, f1); o.x = f0 * inv; o.y = f1 * inv;
            upk2(acc1, f0, f1); o.z = f0 * inv; o.w = f1 * inv;
            *(float4*)&sO[tq * 68 + h8] = o;
            upk2(acc2, f0, f1); o.x = f0 * inv; o.y = f1 * inv;
            upk2(acc3, f0, f1); o.z = f0 * inv; o.w = f1 * inv;
            *(float4*)&sO[tq * 68 + h8 + 4] = o;
        }
    }
    __syncthreads();

    // ---------------- MLP stage 1: sM = gelu(sO @ W15^T + b15) ----------------
    float* sM = sQ;        // stride 68, 4352 floats (spills into dead sK region)
    {
        const float* sO = sH;
        const float* w  = sWc;                     // W15t [64][64]
        unsigned long long a[2][4];
        #pragma unroll
        for (int r = 0; r < 2; r++)
            #pragma unroll
            for (int p = 0; p < 4; p++) a[r][p] = 0ull;

        const float* oR0 = sO + t0 * 68;
        const float* oR1 = oR0 + 68;
        #pragma unroll 2
        for (int c4 = 0; c4 < 16; c4++) {
            float4 h0v = *(const float4*)(oR0 + (c4 << 2));
            float4 h1v = *(const float4*)(oR1 + (c4 << 2));
            float h0a[4] = {h0v.x, h0v.y, h0v.z, h0v.w};
            float h1a[4] = {h1v.x, h1v.y, h1v.z, h1v.w};
            #pragma unroll
            for (int i = 0; i < 4; i++) {
                int c = (c4 << 2) + i;
                ulonglong2 w0 = *(const ulonglong2*)(w + c * 64 + j0);
                ulonglong2 w1 = *(const ulonglong2*)(w + c * 64 + j0 + 32);
                unsigned long long H0 = pk2(h0a[i]);
                unsigned long long H1 = pk2(h1a[i]);
                a[0][0] = fma2(H0, w0.x, a[0][0]); a[0][1] = fma2(H0, w0.y, a[0][1]);
                a[0][2] = fma2(H0, w1.x, a[0][2]); a[0][3] = fma2(H0, w1.y, a[0][3]);
                a[1][0] = fma2(H1, w0.x, a[1][0]); a[1][1] = fma2(H1, w0.y, a[1][1]);
                a[1][2] = fma2(H1, w1.x, a[1][2]); a[1][3] = fma2(H1, w1.y, a[1][3]);
            }
        }
        #pragma unroll
        for (int r = 0; r < 2; r++)
            epi_store(sM + (t0 + r) * 68, a[r], b15, j0, true);
    }
    __syncthreads();

    // ---------------- MLP stage 2: out = sM @ W16^T + b16 -> GMEM ----------------
    {
        const float* w = sH + 4352;                // W16t [64][64]
        unsigned long long a[2][4];
        #pragma unroll
        for (int r = 0; r < 2; r++)
            #pragma unroll
            for (int p = 0; p < 4; p++) a[r][p] = 0ull;

        const float* mR0 = sM + t0 * 68;
        const float* mR1 = mR0 + 68;
        #pragma unroll 2
        for (int c4 = 0; c4 < 16; c4++) {
            float4 h0v = *(const float4*)(mR0 + (c4 << 2));
            float4 h1v = *(const float4*)(mR1 + (c4 << 2));
            float h0a[4] = {h0v.x, h0v.y, h0v.z, h0v.w};
            float h1a[4] = {h1v.x, h1v.y, h1v.z, h1v.w};
            #pragma unroll
            for (int i = 0; i < 4; i++) {
                int c = (c4 << 2) + i;
                ulonglong2 w0 = *(const ulonglong2*)(w + c * 64 + j0);
                ulonglong2 w1 = *(const ulonglong2*)(w + c * 64 + j0 + 32);
                unsigned long long H0 = pk2(h0a[i]);
                unsigned long long H1 = pk2(h1a[i]);
                a[0][0] = fma2(H0, w0.x, a[0][0]); a[0][1] = fma2(H0, w0.y, a[0][1]);
                a[0][2] = fma2(H0, w1.x, a[0][2]); a[0][3] = fma2(H0, w1.y, a[0][3]);
                a[1][0] = fma2(H1, w0.x, a[1][0]); a[1][1] = fma2(H1, w0.y, a[1][1]);
                a[1][2] = fma2(H1, w1.x, a[1][2]); a[1][3] = fma2(H1, w1.y, a[1][3]);
            }
        }

        #pragma unroll
        for (int r = 0; r < 2; r++) {
            float f0, f1;
            float4 oA, oB;
            upk2(a[r][0], f0, f1); oA.x = f0 + b16[j0];      oA.y = f1 + b16[j0 + 1];
            upk2(a[r][1], f0, f1); oA.z = f0 + b16[j0 + 2];  oA.w = f1 + b16[j0 + 3];
            upk2(a[r][2], f0, f1); oB.x = f0 + b16[j0 + 32]; oB.y = f1 + b16[j0 + 33];
            upk2(a[r][3], f0, f1); oB.z = f0 + b16[j0 + 34]; oB.w = f1 + b16[j0 + 35];
            int g = baseX + (t0 + r) * ND_ + j0;
            *(float4*)&out[g]      = oA;
            *(float4*)&out[g + 32] = oB;
        }
    }
}

extern "C" void kernel_launch(void* const* d_in, const int* in_sizes, int n_in,
                              void* d_out, int out_size)
{
    const float* X   = (const float*)d_in[0];
    const float* STE = (const float*)d_in[1];
    const float* W12 = (const float*)d_in[2];
    const float* b12 = (const float*)d_in[3];
    const float* W13 = (const float*)d_in[4];
    const float* b13 = (const float*)d_in[5];
    const float* W14 = (const float*)d_in[6];
    const float* b14 = (const float*)d_in[7];
    const float* W15 = (const float*)d_in[8];
    const float* b15 = (const float*)d_in[9];
    const float* W16 = (const float*)d_in[10];
    const float* b16 = (const float*)d_in[11];
    float* out = (float*)d_out;

    cudaFuncSetAttribute(tam_kernel,
                         cudaFuncAttributeMaxDynamicSharedMemorySize,
                         SMEM_FLOATS * (int)sizeof(float));

    transpose_weights<<<128, 256>>>(W12, W13, W14, W15, W16);

    dim3 grid(N_, B_);
    tam_kernel<<<grid, 256, SMEM_FLOATS * sizeof(float)>>>(
        X, STE, b12, b13, b14, b15, b16, out);
}

// round 13
// speedup vs baseline: 2.4112x; 1.4059x over previous
#include <cuda_runtime.h>
#include <math.h>

#define B_    16
#define T_    64
#define N_    256
#define D_    64
#define TWOD_ 128
#define ND_   16384   // N_*D_ : element stride between consecutive t rows

// Pre-transposed weights: W12t,W13t,W14t as [128][64]; W15t,W16t as [64][64]
__device__ __align__(16) float g_Wt[3 * TWOD_ * D_ + 2 * D_ * D_];   // 32768 floats

__global__ void transpose_weights(const float* __restrict__ W12,
                                  const float* __restrict__ W13,
                                  const float* __restrict__ W14,
                                  const float* __restrict__ W15,
                                  const float* __restrict__ W16)
{
    int idx = blockIdx.x * blockDim.x + threadIdx.x;
    if (idx < 8192) {
        int j = idx >> 7, c = idx & 127;
        g_Wt[c * 64 + j] = W12[idx];
    } else if (idx < 16384) {
        int k = idx - 8192; int j = k >> 7, c = k & 127;
        g_Wt[8192 + c * 64 + j] = W13[k];
    } else if (idx < 24576) {
        int k = idx - 16384; int j = k >> 7, c = k & 127;
        g_Wt[16384 + c * 64 + j] = W14[k];
    } else if (idx < 28672) {
        int k = idx - 24576; int j = k >> 6, c = k & 63;
        g_Wt[24576 + c * 64 + j] = W15[k];
    } else if (idx < 32768) {
        int k = idx - 28672; int j = k >> 6, c = k & 63;
        g_Wt[28672 + c * 64 + j] = W16[k];
    }
}

// ---------------- packed fp32x2 helpers (sm_103a FFMA2 path, PTX-only) ----------------
__device__ __forceinline__ unsigned long long pk2(float v) {
    unsigned long long r;
    asm("mov.b64 %0, {%1, %2};" : "=l"(r) : "f"(v), "f"(v));
    return r;
}
__device__ __forceinline__ void upk2(unsigned long long v, float& lo, float& hi) {
    asm("mov.b64 {%0, %1}, %2;" : "=f"(lo), "=f"(hi) : "l"(v));
}
__device__ __forceinline__ unsigned long long fma2(unsigned long long a,
                                                   unsigned long long b,
                                                   unsigned long long c) {
    unsigned long long d;
    asm("fma.rn.f32x2 %0, %1, %2, %3;" : "=l"(d) : "l"(a), "l"(b), "l"(c));
    return d;
}
__device__ __forceinline__ unsigned long long mul2(unsigned long long a,
                                                   unsigned long long b) {
    unsigned long long d;
    asm("mul.rn.f32x2 %0, %1, %2;" : "=l"(d) : "l"(a), "l"(b));
    return d;
}
__device__ __forceinline__ float psum2(unsigned long long v) {
    float lo, hi; upk2(v, lo, hi); return lo + hi;
}

__device__ __forceinline__ float gelu_f(float x) {
    // exact erf GELU (matches jax.nn.gelu(approximate=False))
    return 0.5f * x * (1.0f + erff(x * 0.7071067811865475f));
}

// SMEM layout (floats):
//   sH  @ 0     : 8704  (H 64x132=8448; reused: sO 64x68 @[0..4352), W16 buf @[4352..8448))
//   sWc @ 8704  : 6144  (QKV chunk: wQ/wK/wV 32x64 each; later W15t full in [0..4096))
//   sQ  @ 14848 : 4096  (later sM 64x68=4352, spilling into dead sK start)
//   sK  @ 18944 : 4096
//   sV  @ 23040 : 4096
// total 27136 floats = 108544 B -> 2 CTAs/SM
#define SMEM_FLOATS 27136

__global__ __launch_bounds__(256, 2)
void tam_kernel(const float* __restrict__ X,  const float* __restrict__ STE,
                const float* __restrict__ b12, const float* __restrict__ b13,
                const float* __restrict__ b14, const float* __restrict__ b15,
                const float* __restrict__ b16, float* __restrict__ out)
{
    extern __shared__ float sm[];
    float* sH  = sm;
    float* sWc = sm + 8704;
    float* sQ  = sm + 14848;
    float* sK  = sm + 18944;
    float* sV  = sm + 23040;

    const int n = blockIdx.x, b = blockIdx.y;
    const int tid = threadIdx.x;
    const int baseX = (b * T_ * N_ + n) * D_;

    // ---------------- load H = [X | STE] : 64 rows x 128, stride 132 ----------------
    for (int i = tid; i < T_ * TWOD_; i += 256) {
        int t = i >> 7, c = i & 127;
        int g = baseX + t * ND_ + (c & 63);
        sH[t * 132 + c] = (c < 64) ? X[g] : STE[g];
    }
    __syncthreads();

    // ================= fused QKV: tile 8t x 2j per thread =================
    // jq = j-pair base (one ulonglong of W per matrix per c), tq8 = 8-row block.
    // Per c-step: 8 H floats + 6 W floats feed 48 FMAs (24 FFMA2).
    const int jq  = (tid & 31) * 2;
    const int tq8 = (tid >> 5) * 8;

    unsigned long long aQ[8], aK[8], aV[8];
    #pragma unroll
    for (int r = 0; r < 8; r++) { aQ[r] = 0ull; aK[r] = 0ull; aV[r] = 0ull; }

    for (int ch = 0; ch < 4; ch++) {               // 4 chunks of 32 c-rows
        // cooperative load of 32x64 chunk of each of W12t/W13t/W14t (6144 floats)
        #pragma unroll
        for (int i = 0; i < 6; i++) {
            int k = i * 256 + tid;                 // float4 index 0..1535
            int m = k >> 9, off = (k & 511) << 2;
            *(float4*)&sWc[m * 2048 + off] =
                *(const float4*)&g_Wt[m * 8192 + ch * 2048 + off];
        }
        __syncthreads();

        #pragma unroll 2
        for (int c2 = 0; c2 < 16; c2++) {
            const int cc = (ch << 5) + (c2 << 1);
            float2 h[8];
            #pragma unroll
            for (int r = 0; r < 8; r++)
                h[r] = *(const float2*)&sH[(tq8 + r) * 132 + cc];

            #pragma unroll
            for (int i = 0; i < 2; i++) {
                const int c = (c2 << 1) + i;
                unsigned long long wq = *(const unsigned long long*)&sWc[c * 64 + jq];
                unsigned long long wk = *(const unsigned long long*)&sWc[2048 + c * 64 + jq];
                unsigned long long wv = *(const unsigned long long*)&sWc[4096 + c * 64 + jq];
                #pragma unroll
                for (int r = 0; r < 8; r++) {
                    unsigned long long Hc = pk2(i ? h[r].y : h[r].x);
                    aQ[r] = fma2(Hc, wq, aQ[r]);
                    aK[r] = fma2(Hc, wk, aK[r]);
                    aV[r] = fma2(Hc, wv, aV[r]);
                }
            }
        }
        __syncthreads();
    }

    // QKV epilogue: bias + exact gelu, store j-pair per row
    {
        const float2 bq = make_float2(b12[jq], b12[jq + 1]);
        const float2 bk = make_float2(b13[jq], b13[jq + 1]);
        const float2 bv = make_float2(b14[jq], b14[jq + 1]);
        #pragma unroll
        for (int r = 0; r < 8; r++) {
            float f0, f1;
            upk2(aQ[r], f0, f1);
            *(float2*)&sQ[(tq8 + r) * 64 + jq] =
                make_float2(gelu_f(f0 + bq.x), gelu_f(f1 + bq.y));
            upk2(aK[r], f0, f1);
            *(float2*)&sK[(tq8 + r) * 64 + jq] =
                make_float2(gelu_f(f0 + bk.x), gelu_f(f1 + bk.y));
            upk2(aV[r], f0, f1);
            *(float2*)&sV[(tq8 + r) * 64 + jq] =
                make_float2(gelu_f(f0 + bv.x), gelu_f(f1 + bv.y));
        }
    }
    __syncthreads();

    // ---------------- overlap: load W15 -> sWc[0..4096), W16 -> sH[4352..8448) ----------------
    #pragma unroll
    for (int i = 0; i < 4; i++) {
        int k = (i * 256 + tid) << 2;              // float offset 0..4092
        *(float4*)&sWc[k]        = *(const float4*)&g_Wt[24576 + k];
        *(float4*)&sH[4352 + k]  = *(const float4*)&g_Wt[28672 + k];
    }

    // ---------------- causal attention: two queries per thread, shared K/V loads ----------------
    // Logits are small enough (gelu-bounded q,k, d=8) that exp cannot overflow fp32;
    // softmax shift-invariance makes skipping the max pass exact up to rounding.
    {
        const int h8 = (tid & 7) * 8;
        const int tA = tid >> 3;                   // query A: tA, query B: tA + 32
        const float scale = 0.35355339059327376f;  // 1/sqrt(8)
        float* sO = sH;                            // output tile, stride 68, in [0..4352)

        const ulonglong2 q1a = *(const ulonglong2*)&sQ[tA * 64 + h8];
        const ulonglong2 q1b = *(const ulonglong2*)&sQ[tA * 64 + h8 + 4];
        const ulonglong2 q2a = *(const ulonglong2*)&sQ[(tA + 32) * 64 + h8];
        const ulonglong2 q2b = *(const ulonglong2*)&sQ[(tA + 32) * 64 + h8 + 4];

        unsigned long long ac1[4] = {0,0,0,0}, ac2[4] = {0,0,0,0};
        float s1 = 0.f, s2 = 0.f;

        // common range: s in [0, tA] — K/V loaded once, both queries updated
        #pragma unroll 2
        for (int s = 0; s <= tA; s++) {
            const ulonglong2 ka = *(const ulonglong2*)&sK[s * 64 + h8];
            const ulonglong2 kb = *(const ulonglong2*)&sK[s * 64 + h8 + 4];
            unsigned long long d1 = mul2(q1a.x, ka.x);
            d1 = fma2(q1a.y, ka.y, d1); d1 = fma2(q1b.x, kb.x, d1); d1 = fma2(q1b.y, kb.y, d1);
            unsigned long long d2 = mul2(q2a.x, ka.x);
            d2 = fma2(q2a.y, ka.y, d2); d2 = fma2(q2b.x, kb.x, d2); d2 = fma2(q2b.y, kb.y, d2);
            float e1 = __expf(psum2(d1) * scale);
            float e2 = __expf(psum2(d2) * scale);
            s1 += e1; s2 += e2;
            const ulonglong2 va = *(const ulonglong2*)&sV[s * 64 + h8];
            const ulonglong2 vb = *(const ulonglong2*)&sV[s * 64 + h8 + 4];
            unsigned long long E1 = pk2(e1), E2 = pk2(e2);
            ac1[0] = fma2(E1, va.x, ac1[0]); ac1[1] = fma2(E1, va.y, ac1[1]);
            ac1[2] = fma2(E1, vb.x, ac1[2]); ac1[3] = fma2(E1, vb.y, ac1[3]);
            ac2[0] = fma2(E2, va.x, ac2[0]); ac2[1] = fma2(E2, va.y, ac2[1]);
            ac2[2] = fma2(E2, vb.x, ac2[2]); ac2[3] = fma2(E2, vb.y, ac2[3]);
        }
        // tail range: s in (tA, tA+32] — query B only; fixed 32 trips, no divergence
        #pragma unroll 4
        for (int k2 = 1; k2 <= 32; k2++) {
            const int s = tA + k2;
            const ulonglong2 ka = *(const ulonglong2*)&sK[s * 64 + h8];
            const ulonglong2 kb = *(const ulonglong2*)&sK[s * 64 + h8 + 4];
            unsigned long long d2 = mul2(q2a.x, ka.x);
            d2 = fma2(q2a.y, ka.y, d2); d2 = fma2(q2b.x, kb.x, d2); d2 = fma2(q2b.y, kb.y, d2);
            float e2 = __expf(psum2(d2) * scale);
            s2 += e2;
            const ulonglong2 va = *(const ulonglong2*)&sV[s * 64 + h8];
            const ulonglong2 vb = *(const ulonglong2*)&sV[s * 64 + h8 + 4];
            unsigned long long E2 = pk2(e2);
            ac2[0] = fma2(E2, va.x, ac2[0]); ac2[1] = fma2(E2, va.y, ac2[1]);
            ac2[2] = fma2(E2, vb.x, ac2[2]); ac2[3] = fma2(E2, vb.y, ac2[3]);
        }

        float inv1 = 1.0f / s1, inv2 = 1.0f / s2;
        float f0, f1;
        float4 o;
        upk2(ac1[0], f0, f1); o.x = f0 * inv1; o.y = f1 * inv1;
        upk2(ac1[1], f0, f1); o.z = f0 * inv1; o.w = f1 * inv1;
        *(float4*)&sO[tA * 68 + h8] = o;
        upk2(ac1[2], f0, f1); o.x = f0 * inv1; o.y = f1 * inv1;
        upk2(ac1[3], f0, f1); o.z = f0 * inv1; o.w = f1 * inv1;
        *(float4*)&sO[tA * 68 + h8 + 4] = o;
        upk2(ac2[0], f0, f1); o.x = f0 * inv2; o.y = f1 * inv2;
        upk2(ac2[1], f0, f1); o.z = f0 * inv2; o.w = f1 * inv2;
        *(float4*)&sO[(tA + 32) * 68 + h8] = o;
        upk2(ac2[2], f0, f1); o.x = f0 * inv2; o.y = f1 * inv2;
        upk2(ac2[3], f0, f1); o.z = f0 * inv2; o.w = f1 * inv2;
        *(float4*)&sO[(tA + 32) * 68 + h8 + 4] = o;
    }
    __syncthreads();

    // ================= MLP stages: tile 4t x 4j per thread =================
    const int jm = (tid & 15) * 4;
    const int tm = (tid >> 4) * 4;
    float* sM = sQ;                                // stride 68 (spills into dead sK)

    // ---------------- MLP stage 1: sM = gelu(sO @ W15^T + b15) ----------------
    {
        const float* sO = sH;
        unsigned long long a[4][2];
        #pragma unroll
        for (int r = 0; r < 4; r++) { a[r][0] = 0ull; a[r][1] = 0ull; }

        #pragma unroll 2
        for (int c4 = 0; c4 < 16; c4++) {
            const int cc = c4 << 2;
            float ha[4][4];
            #pragma unroll
            for (int r = 0; r < 4; r++) {
                float4 hv = *(const float4*)&sO[(tm + r) * 68 + cc];
                ha[r][0] = hv.x; ha[r][1] = hv.y; ha[r][2] = hv.z; ha[r][3] = hv.w;
            }
            #pragma unroll
            for (int i = 0; i < 4; i++) {
                const ulonglong2 w = *(const ulonglong2*)&sWc[(cc + i) * 64 + jm];
                #pragma unroll
                for (int r = 0; r < 4; r++) {
                    unsigned long long Hc = pk2(ha[r][i]);
                    a[r][0] = fma2(Hc, w.x, a[r][0]);
                    a[r][1] = fma2(Hc, w.y, a[r][1]);
                }
            }
        }
        const float4 bb = *(const float4*)&b15[jm];
        #pragma unroll
        for (int r = 0; r < 4; r++) {
            float f0, f1, f2, f3;
            upk2(a[r][0], f0, f1);
            upk2(a[r][1], f2, f3);
            float4 o;
            o.x = gelu_f(f0 + bb.x); o.y = gelu_f(f1 + bb.y);
            o.z = gelu_f(f2 + bb.z); o.w = gelu_f(f3 + bb.w);
            *(float4*)&sM[(tm + r) * 68 + jm] = o;
        }
    }
    __syncthreads();

    // ---------------- MLP stage 2: out = sM @ W16^T + b16 -> GMEM ----------------
    {
        const float* w16 = sH + 4352;              // W16t [64][64]
        unsigned long long a[4][2];
        #pragma unroll
        for (int r = 0; r < 4; r++) { a[r][0] = 0ull; a[r][1] = 0ull; }

        #pragma unroll 2
        for (int c4 = 0; c4 < 16; c4++) {
            const int cc = c4 << 2;
            float ha[4][4];
            #pragma unroll
            for (int r = 0; r < 4; r++) {
                float4 hv = *(const float4*)&sM[(tm + r) * 68 + cc];
                ha[r][0] = hv.x; ha[r][1] = hv.y; ha[r][2] = hv.z; ha[r][3] = hv.w;
            }
            #pragma unroll
            for (int i = 0; i < 4; i++) {
                const ulonglong2 w = *(const ulonglong2*)&w16[(cc + i) * 64 + jm];
                #pragma unroll
                for (int r = 0; r < 4; r++) {
                    unsigned long long Hc = pk2(ha[r][i]);
                    a[r][0] = fma2(Hc, w.x, a[r][0]);
                    a[r][1] = fma2(Hc, w.y, a[r][1]);
                }
            }
        }
        const float4 bb = *(const float4*)&b16[jm];
        #pragma unroll
        for (int r = 0; r < 4; r++) {
            float f0, f1, f2, f3;
            upk2(a[r][0], f0, f1);
            upk2(a[r][1], f2, f3);
            float4 o;
            o.x = f0 + bb.x; o.y = f1 + bb.y; o.z = f2 + bb.z; o.w = f3 + bb.w;
            *(float4*)&out[baseX + (tm + r) * ND_ + jm] = o;
        }
    }
}

extern "C" void kernel_launch(void* const* d_in, const int* in_sizes, int n_in,
                              void* d_out, int out_size)
{
    const float* X   = (const float*)d_in[0];
    const float* STE = (const float*)d_in[1];
    const float* W12 = (const float*)d_in[2];
    const float* b12 = (const float*)d_in[3];
    const float* W13 = (const float*)d_in[4];
    const float* b13 = (const float*)d_in[5];
    const float* W14 = (const float*)d_in[6];
    const float* b14 = (const float*)d_in[7];
    const float* W15 = (const float*)d_in[8];
    const float* b15 = (const float*)d_in[9];
    const float* W16 = (const float*)d_in[10];
    const float* b16 = (const float*)d_in[11];
    float* out = (float*)d_out;

    cudaFuncSetAttribute(tam_kernel,
                         cudaFuncAttributeMaxDynamicSharedMemorySize,
                         SMEM_FLOATS * (int)sizeof(float));

    transpose_weights<<<128, 256>>>(W12, W13, W14, W15, W16);

    dim3 grid(N_, B_);
    tam_kernel<<<grid, 256, SMEM_FLOATS * sizeof(float)>>>(
        X, STE, b12, b13, b14, b15, b16, out);
}